// round 1
// baseline (speedup 1.0000x reference)
#include <cuda_runtime.h>

// ---------------------------------------------------------------------------
// GraphEncoder relative-position attention, GB300 sm_103a
// Fixed shapes: B=2, S=2048, H=768, NH=12, D=64, R=256, MAX_REL=128
//
// Kernel 1: fused QKV projection GEMM (Q pre-scaled by 1/8), output in
//           [B, NH, S, D] layout.
// Kernel 2: flash attention with online softmax; relative key bias served
//           from an in-smem per-row 256-bucket cache (computed in-kernel);
//           relative value term via clamp-bucket identity:
//              ctx_rel[i,:] = sum_j p_ij * rve[clip(j-i,-128,127)+128,:]
//           with out-of-band tiles collapsed to scalar accumulators.
// ---------------------------------------------------------------------------

namespace {
constexpr int Bn  = 2;
constexpr int Sn  = 2048;
constexpr int Hn  = 768;
constexpr int NHn = 12;
constexpr int Dn  = 64;

// dynamic smem layout (floats) for attention kernel
constexpr int QST   = 0;                  // Q transposed  [d][m]   64x64
constexpr int KSTo  = 4096;               // K transposed  [d][n]   64x64
constexpr int VSo   = 8192;               // V natural     [n][d]   64x64
constexpr int PSo   = 12288;              // P             [m][n]   64x65 (pad)
constexpr int RELCo = PSo + 64 * 65;      // rel cache     [m][r]   64x256
constexpr int MBo   = RELCo + 64 * 256;   // mask bias     [n]      64
constexpr int SMEMF = MBo + 64;           // total floats = 32896 -> 131584 B
}

__device__ float g_Q[Bn * NHn * Sn * Dn];
__device__ float g_K[Bn * NHn * Sn * Dn];
__device__ float g_V[Bn * NHn * Sn * Dn];

// XOR swizzle for transposed [d][m] tiles: keeps 4-aligned float4 groups,
// spreads the stride-64 transpose stores across banks (<=2-way conflicts).
__device__ __forceinline__ int swz(int d, int m) {
    return d * 64 + (m ^ (((d >> 2) & 15) << 2));
}

// ---------------------------------------------------------------------------
// Kernel 1: X[4096,768] @ W[768,768] + b  -> [B,NH,S,D] heads layout
// blockIdx.z selects Q/K/V. Q is multiplied by 1/sqrt(D) = 0.125.
// 128x128 tile, BK=16, 256 threads, 8x8 per-thread microtile (split 4+4).
// ---------------------------------------------------------------------------
__global__ __launch_bounds__(256) void qkv_kernel(
    const float* __restrict__ X,
    const float* __restrict__ Wq, const float* __restrict__ bq,
    const float* __restrict__ Wk, const float* __restrict__ bk,
    const float* __restrict__ Wv, const float* __restrict__ bv)
{
    __shared__ float As[16][128];   // X^T chunk: As[k][m]
    __shared__ float Bs[16][128];   // W chunk:   Bs[k][n]

    const int z = blockIdx.z;
    const float* Wp   = (z == 0) ? Wq : ((z == 1) ? Wk : Wv);
    const float* bp   = (z == 0) ? bq : ((z == 1) ? bk : bv);
    float*       outp = (z == 0) ? g_Q : ((z == 1) ? g_K : g_V);
    const float  sc   = (z == 0) ? 0.125f : 1.0f;

    const int r0 = blockIdx.x * 128;
    const int c0 = blockIdx.y * 128;
    const int tid = threadIdx.x;
    const int ty = tid >> 4, tx = tid & 15;

    float acc[8][8] = {};

    for (int kt = 0; kt < 768; kt += 16) {
        // load X block transposed into As
        #pragma unroll
        for (int s2 = 0; s2 < 2; s2++) {
            int f = tid + s2 * 256;
            int row = f >> 2, cg = f & 3;
            float4 v = *(const float4*)(X + (size_t)(r0 + row) * 768 + kt + cg * 4);
            As[cg * 4 + 0][row] = v.x;
            As[cg * 4 + 1][row] = v.y;
            As[cg * 4 + 2][row] = v.z;
            As[cg * 4 + 3][row] = v.w;
        }
        // load W block into Bs
        #pragma unroll
        for (int s2 = 0; s2 < 2; s2++) {
            int f = tid + s2 * 256;
            int kr = f >> 5, cg = f & 31;
            *(float4*)(&Bs[kr][cg * 4]) =
                *(const float4*)(Wp + (size_t)(kt + kr) * 768 + c0 + cg * 4);
        }
        __syncthreads();

        #pragma unroll
        for (int k = 0; k < 16; k++) {
            float a[8], bb[8];
            *(float4*)(a)      = *(const float4*)&As[k][ty * 4];
            *(float4*)(a + 4)  = *(const float4*)&As[k][64 + ty * 4];
            *(float4*)(bb)     = *(const float4*)&Bs[k][tx * 4];
            *(float4*)(bb + 4) = *(const float4*)&Bs[k][64 + tx * 4];
            #pragma unroll
            for (int i = 0; i < 8; i++)
                #pragma unroll
                for (int j = 0; j < 8; j++)
                    acc[i][j] = fmaf(a[i], bb[j], acc[i][j]);
        }
        __syncthreads();
    }

    // epilogue: add bias, scale, scatter to [B,NH,S,D]
    #pragma unroll
    for (int i = 0; i < 8; i++) {
        int r = r0 + ((i < 4) ? (ty * 4 + i) : (64 + ty * 4 + (i - 4)));
        int b = r >> 11, s = r & 2047;
        #pragma unroll
        for (int jg = 0; jg < 2; jg++) {
            int c = c0 + ((jg == 0) ? (tx * 4) : (64 + tx * 4));
            int h = c >> 6, d = c & 63;
            float4 o;
            o.x = (acc[i][jg * 4 + 0] + bp[c + 0]) * sc;
            o.y = (acc[i][jg * 4 + 1] + bp[c + 1]) * sc;
            o.z = (acc[i][jg * 4 + 2] + bp[c + 2]) * sc;
            o.w = (acc[i][jg * 4 + 3] + bp[c + 3]) * sc;
            *(float4*)(outp + ((size_t)(b * NHn + h) * Sn + s) * Dn + d) = o;
        }
    }
}

// ---------------------------------------------------------------------------
// Kernel 2: flash attention with relative-position bias.
// grid (S/64, NH, B), 256 threads. Thread (cy, cx) owns rows i0+4cy..+3 and
// (score phase) cols j0+4cx..+3 / (PV phase) dims 4cx..+3.
// ---------------------------------------------------------------------------
__global__ __launch_bounds__(256, 1) void attn_kernel(
    const float* __restrict__ mask,
    const float* __restrict__ rke,
    const float* __restrict__ rve,
    float* __restrict__ out)
{
    extern __shared__ float sm[];
    const int tid = threadIdx.x;
    const int cy = tid >> 4, cx = tid & 15;
    const int hq = blockIdx.y, bz = blockIdx.z;
    const int bh = bz * NHn + hq;
    const int i0 = blockIdx.x * 64;

    const float* Qg = g_Q + ((size_t)bh * Sn + i0) * Dn;
    const float* Kg = g_K + (size_t)bh * Sn * Dn;
    const float* Vg = g_V + (size_t)bh * Sn * Dn;

    // ---- load Q tile, transposed + swizzled ----
    #pragma unroll
    for (int s2 = 0; s2 < 4; s2++) {
        int f = tid + s2 * 256;
        int m = f >> 4, dg = f & 15;
        float4 v = *(const float4*)(Qg + m * 64 + dg * 4);
        sm[QST + swz(dg * 4 + 0, m)] = v.x;
        sm[QST + swz(dg * 4 + 1, m)] = v.y;
        sm[QST + swz(dg * 4 + 2, m)] = v.z;
        sm[QST + swz(dg * 4 + 3, m)] = v.w;
    }
    __syncthreads();

    // ---- relative-key cache: relc[m][r] = q_m . rke_r (scale already in Q) ----
    for (int rc = 0; rc < 4; rc++) {
        #pragma unroll
        for (int s2 = 0; s2 < 4; s2++) {
            int f = tid + s2 * 256;
            int n = f >> 4, dg = f & 15;
            float4 v = *(const float4*)(rke + (rc * 64 + n) * 64 + dg * 4);
            sm[KSTo + swz(dg * 4 + 0, n)] = v.x;
            sm[KSTo + swz(dg * 4 + 1, n)] = v.y;
            sm[KSTo + swz(dg * 4 + 2, n)] = v.z;
            sm[KSTo + swz(dg * 4 + 3, n)] = v.w;
        }
        __syncthreads();
        float t[4][4] = {};
        #pragma unroll
        for (int d = 0; d < 64; d++) {
            float4 q4 = *(const float4*)&sm[QST + swz(d, cy * 4)];
            float4 k4 = *(const float4*)&sm[KSTo + swz(d, cx * 4)];
            float qa[4] = {q4.x, q4.y, q4.z, q4.w};
            float ka[4] = {k4.x, k4.y, k4.z, k4.w};
            #pragma unroll
            for (int ri = 0; ri < 4; ri++)
                #pragma unroll
                for (int ni = 0; ni < 4; ni++)
                    t[ri][ni] = fmaf(qa[ri], ka[ni], t[ri][ni]);
        }
        #pragma unroll
        for (int ri = 0; ri < 4; ri++)
            #pragma unroll
            for (int ni = 0; ni < 4; ni++)
                sm[RELCo + (cy * 4 + ri) * 256 + rc * 64 + cx * 4 + ni] = t[ri][ni];
        __syncthreads();
    }

    // ---- accumulators ----
    float o[4][4] = {}, orl[4][4] = {};
    float mu[4], l[4] = {}, plo[4] = {}, phi[4] = {};
    #pragma unroll
    for (int ri = 0; ri < 4; ri++) mu[ri] = -1e30f;

    for (int jt = 0; jt < 32; jt++) {
        const int j0 = jt * 64;
        __syncthreads();   // protect previous iteration's P/V reads

        // ---- load K (transposed+swizzled), V (natural), mask bias ----
        #pragma unroll
        for (int s2 = 0; s2 < 4; s2++) {
            int f = tid + s2 * 256;
            int n = f >> 4, dg = f & 15;
            float4 v = *(const float4*)(Kg + (size_t)(j0 + n) * 64 + dg * 4);
            sm[KSTo + swz(dg * 4 + 0, n)] = v.x;
            sm[KSTo + swz(dg * 4 + 1, n)] = v.y;
            sm[KSTo + swz(dg * 4 + 2, n)] = v.z;
            sm[KSTo + swz(dg * 4 + 3, n)] = v.w;
            float4 w = *(const float4*)(Vg + (size_t)(j0 + n) * 64 + dg * 4);
            *(float4*)&sm[VSo + n * 64 + dg * 4] = w;
        }
        if (tid < 64)
            sm[MBo + tid] = (1.0f - mask[bz * Sn + j0 + tid]) * -10000.0f;
        __syncthreads();

        // ---- scores: p[ri][ni] = q_i . k_j  (scale folded into Q) ----
        float p[4][4] = {};
        #pragma unroll
        for (int d = 0; d < 64; d++) {
            float4 q4 = *(const float4*)&sm[QST + swz(d, cy * 4)];
            float4 k4 = *(const float4*)&sm[KSTo + swz(d, cx * 4)];
            float qa[4] = {q4.x, q4.y, q4.z, q4.w};
            float ka[4] = {k4.x, k4.y, k4.z, k4.w};
            #pragma unroll
            for (int ri = 0; ri < 4; ri++)
                #pragma unroll
                for (int ni = 0; ni < 4; ni++)
                    p[ri][ni] = fmaf(qa[ri], ka[ni], p[ri][ni]);
        }

        const bool pure_lo = (j0 + 63 - i0 <= -128);
        const bool pure_hi = (j0 - (i0 + 63) >= 127);
        const bool mixed = !pure_lo && !pure_hi;

        // ---- add relative key bias + mask bias ----
        #pragma unroll
        for (int ri = 0; ri < 4; ri++) {
            int i = i0 + cy * 4 + ri;
            #pragma unroll
            for (int ni = 0; ni < 4; ni++) {
                int j = j0 + cx * 4 + ni;
                int bkt = j - i;
                bkt = max(-128, min(127, bkt)) + 128;
                p[ri][ni] += sm[RELCo + (cy * 4 + ri) * 256 + bkt]
                           + sm[MBo + cx * 4 + ni];
            }
        }

        // ---- online softmax update (rows distributed over 16 cx lanes) ----
        #pragma unroll
        for (int ri = 0; ri < 4; ri++) {
            float rm = fmaxf(fmaxf(p[ri][0], p[ri][1]), fmaxf(p[ri][2], p[ri][3]));
            rm = fmaxf(rm, __shfl_xor_sync(0xffffffffu, rm, 1));
            rm = fmaxf(rm, __shfl_xor_sync(0xffffffffu, rm, 2));
            rm = fmaxf(rm, __shfl_xor_sync(0xffffffffu, rm, 4));
            rm = fmaxf(rm, __shfl_xor_sync(0xffffffffu, rm, 8));
            float nm = fmaxf(mu[ri], rm);
            float al = __expf(mu[ri] - nm);
            mu[ri] = nm;
            float rs = 0.f;
            #pragma unroll
            for (int ni = 0; ni < 4; ni++) {
                p[ri][ni] = __expf(p[ri][ni] - nm);
                rs += p[ri][ni];
            }
            rs += __shfl_xor_sync(0xffffffffu, rs, 1);
            rs += __shfl_xor_sync(0xffffffffu, rs, 2);
            rs += __shfl_xor_sync(0xffffffffu, rs, 4);
            rs += __shfl_xor_sync(0xffffffffu, rs, 8);
            l[ri] = l[ri] * al + rs;
            plo[ri] *= al;
            phi[ri] *= al;
            if (pure_lo) plo[ri] += rs;
            if (pure_hi) phi[ri] += rs;
            #pragma unroll
            for (int di = 0; di < 4; di++) { o[ri][di] *= al; orl[ri][di] *= al; }
        }

        // ---- stage P (padded stride 65) ----
        #pragma unroll
        for (int ri = 0; ri < 4; ri++)
            #pragma unroll
            for (int ni = 0; ni < 4; ni++)
                sm[PSo + (cy * 4 + ri) * 65 + cx * 4 + ni] = p[ri][ni];
        __syncthreads();

        // ---- PV accumulation (+ in-band relative value term) ----
        if (mixed) {
            #pragma unroll 2
            for (int n = 0; n < 64; n++) {
                float pr[4];
                #pragma unroll
                for (int ri = 0; ri < 4; ri++)
                    pr[ri] = sm[PSo + (cy * 4 + ri) * 65 + n];
                float4 v4 = *(const float4*)&sm[VSo + n * 64 + cx * 4];
                #pragma unroll
                for (int ri = 0; ri < 4; ri++) {
                    o[ri][0] = fmaf(pr[ri], v4.x, o[ri][0]);
                    o[ri][1] = fmaf(pr[ri], v4.y, o[ri][1]);
                    o[ri][2] = fmaf(pr[ri], v4.z, o[ri][2]);
                    o[ri][3] = fmaf(pr[ri], v4.w, o[ri][3]);
                }
                int jg = j0 + n;
                #pragma unroll
                for (int ri = 0; ri < 4; ri++) {
                    int dlt = jg - (i0 + cy * 4 + ri);
                    int bkt = max(-128, min(127, dlt)) + 128;
                    float4 rv = __ldg((const float4*)(rve + bkt * 64 + cx * 4));
                    orl[ri][0] = fmaf(pr[ri], rv.x, orl[ri][0]);
                    orl[ri][1] = fmaf(pr[ri], rv.y, orl[ri][1]);
                    orl[ri][2] = fmaf(pr[ri], rv.z, orl[ri][2]);
                    orl[ri][3] = fmaf(pr[ri], rv.w, orl[ri][3]);
                }
            }
        } else {
            #pragma unroll 4
            for (int n = 0; n < 64; n++) {
                float pr[4];
                #pragma unroll
                for (int ri = 0; ri < 4; ri++)
                    pr[ri] = sm[PSo + (cy * 4 + ri) * 65 + n];
                float4 v4 = *(const float4*)&sm[VSo + n * 64 + cx * 4];
                #pragma unroll
                for (int ri = 0; ri < 4; ri++) {
                    o[ri][0] = fmaf(pr[ri], v4.x, o[ri][0]);
                    o[ri][1] = fmaf(pr[ri], v4.y, o[ri][1]);
                    o[ri][2] = fmaf(pr[ri], v4.z, o[ri][2]);
                    o[ri][3] = fmaf(pr[ri], v4.w, o[ri][3]);
                }
            }
        }
    }

    // ---- epilogue: out-of-band rve terms, normalize, write [B,S,H] ----
    float4 rv0 = __ldg((const float4*)(rve + 0 * 64 + cx * 4));
    float4 rvN = __ldg((const float4*)(rve + 255 * 64 + cx * 4));
    #pragma unroll
    for (int ri = 0; ri < 4; ri++) {
        float inv = 1.0f / l[ri];
        int row = i0 + cy * 4 + ri;
        float4 res;
        res.x = (o[ri][0] + orl[ri][0] + plo[ri] * rv0.x + phi[ri] * rvN.x) * inv;
        res.y = (o[ri][1] + orl[ri][1] + plo[ri] * rv0.y + phi[ri] * rvN.y) * inv;
        res.z = (o[ri][2] + orl[ri][2] + plo[ri] * rv0.z + phi[ri] * rvN.z) * inv;
        res.w = (o[ri][3] + orl[ri][3] + plo[ri] * rv0.w + phi[ri] * rvN.w) * inv;
        *(float4*)(out + ((size_t)bz * Sn + row) * Hn + hq * 64 + cx * 4) = res;
    }
}

// ---------------------------------------------------------------------------
extern "C" void kernel_launch(void* const* d_in, const int* in_sizes, int n_in,
                              void* d_out, int out_size)
{
    const float* X    = (const float*)d_in[0];
    const float* mask = (const float*)d_in[1];
    const float* Wq   = (const float*)d_in[2];
    const float* bq   = (const float*)d_in[3];
    const float* Wk   = (const float*)d_in[4];
    const float* bk   = (const float*)d_in[5];
    const float* Wv   = (const float*)d_in[6];
    const float* bv   = (const float*)d_in[7];
    const float* rke  = (const float*)d_in[8];
    const float* rve  = (const float*)d_in[9];
    // d_in[10] = indices: recomputed analytically in-kernel, not needed.
    float* out = (float*)d_out;

    (void)in_sizes; (void)n_in; (void)out_size;

    cudaFuncSetAttribute(attn_kernel,
                         cudaFuncAttributeMaxDynamicSharedMemorySize,
                         SMEMF * (int)sizeof(float));

    qkv_kernel<<<dim3(32, 6, 3), 256>>>(X, Wq, bq, Wk, bk, Wv, bv);
    attn_kernel<<<dim3(32, NHn, Bn), 256, SMEMF * sizeof(float)>>>(mask, rke, rve, out);
}